// round 17
// baseline (speedup 1.0000x reference)
#include <cuda_runtime.h>
#include <cuda_bf16.h>

// out[n,:] = trace-contraction of the Jacobian of the antisymmetric field
// A(p)=M-M^T (M upper-tri from v=MLP(p), 3->32->32->32->3, softplus beta=20):
//   out0 =  Jv[0][1] + Jv[1][2]
//   out1 = -Jv[0][0] + Jv[2][2]
//   out2 = -Jv[1][0] - Jv[2][1],   Jv[c][j] = dv_c/dx_j
// Forward (sigmoid(20z) diagonals) + 3 simultaneous forward-mode tangents.
//
// R16 = R15 (dual sample groups: each lane processes TWO samples, 16/warp, so
// every weight LDS.128 feeds both groups -> weight-LDS/sample halves) with the
// alignment bug fixed: weight block stride back to 80B (10 ulls, 16B-aligned;
// R15's 72B stride made odd blocks 8-mod-16 -> misaligned LDS.128 trap).
// q byte-offsets {0,80,32,112} mod 128 -> 4 distinct bank groups, 1 wavefront.

#define BETAF 20.0f
#define INV_BETAF 0.05f
#define BLOCK 32
#define GRID 1064   // 152 SMs x 7 resident 1-warp blocks, persistent loop

typedef unsigned long long ull;

__device__ __forceinline__ ull pk2(float lo, float hi) {
    ull d;
    asm("mov.b64 %0, {%1, %2};" : "=l"(d)
        : "r"(__float_as_uint(lo)), "r"(__float_as_uint(hi)));
    return d;
}
__device__ __forceinline__ float hadd2(ull s) {
    unsigned l, h;
    asm("mov.b64 {%0, %1}, %2;" : "=r"(l), "=r"(h) : "l"(s));
    return __uint_as_float(l) + __uint_as_float(h);
}
#define FMA2(d,a,b,c) asm("fma.rn.f32x2 %0, %1, %2, %3;" : "=l"(d) : "l"(a), "l"(b), "l"(c))

__device__ __forceinline__ void act_hd(float z, float& h, float& d) {
    float y = BETAF * z;
    float e = __expf(-fabsf(y));
    float r = __fdividef(1.0f, 1.0f + e);
    d = (y >= 0.0f) ? r : e * r;                       // sigmoid(20z)
    h = fmaxf(z, 0.0f) + __logf(1.0f + e) * INV_BETAF; // softplus(20z)/20
}
__device__ __forceinline__ float act_d(float z) {
    float y = BETAF * z;
    float e = __expf(-fabsf(y));
    float r = __fdividef(1.0f, 1.0f + e);
    return (y >= 0.0f) ? r : e * r;
}

// one k-pair micro-step for BOTH sample groups: 4 weight LDS.128, 64 FMA2
#define KP(WB, kp, hA, u0A, u1A, u2A, hB, u0B, u1B, u2B) { \
    const ulonglong2* wp_ = (const ulonglong2*)((WB) + ((kp)*4 + q)*10); \
    const ulonglong2 wa = wp_[0], wb = wp_[1], wc = wp_[2], wd = wp_[3]; \
    FMA2(fA0,hA,wa.x,fA0); FMA2(fA1,hA,wa.y,fA1); FMA2(fA2,hA,wb.x,fA2); FMA2(fA3,hA,wb.y,fA3); \
    FMA2(fA4,hA,wc.x,fA4); FMA2(fA5,hA,wc.y,fA5); FMA2(fA6,hA,wd.x,fA6); FMA2(fA7,hA,wd.y,fA7); \
    FMA2(paA0,u0A,wa.x,paA0); FMA2(paA1,u0A,wa.y,paA1); FMA2(paA2,u0A,wb.x,paA2); FMA2(paA3,u0A,wb.y,paA3); \
    FMA2(paA4,u0A,wc.x,paA4); FMA2(paA5,u0A,wc.y,paA5); FMA2(paA6,u0A,wd.x,paA6); FMA2(paA7,u0A,wd.y,paA7); \
    FMA2(pbA0,u1A,wa.x,pbA0); FMA2(pbA1,u1A,wa.y,pbA1); FMA2(pbA2,u1A,wb.x,pbA2); FMA2(pbA3,u1A,wb.y,pbA3); \
    FMA2(pbA4,u1A,wc.x,pbA4); FMA2(pbA5,u1A,wc.y,pbA5); FMA2(pbA6,u1A,wd.x,pbA6); FMA2(pbA7,u1A,wd.y,pbA7); \
    FMA2(pcA0,u2A,wa.x,pcA0); FMA2(pcA1,u2A,wa.y,pcA1); FMA2(pcA2,u2A,wb.x,pcA2); FMA2(pcA3,u2A,wb.y,pcA3); \
    FMA2(pcA4,u2A,wc.x,pcA4); FMA2(pcA5,u2A,wc.y,pcA5); FMA2(pcA6,u2A,wd.x,pcA6); FMA2(pcA7,u2A,wd.y,pcA7); \
    FMA2(fB0,hB,wa.x,fB0); FMA2(fB1,hB,wa.y,fB1); FMA2(fB2,hB,wb.x,fB2); FMA2(fB3,hB,wb.y,fB3); \
    FMA2(fB4,hB,wc.x,fB4); FMA2(fB5,hB,wc.y,fB5); FMA2(fB6,hB,wd.x,fB6); FMA2(fB7,hB,wd.y,fB7); \
    FMA2(paB0,u0B,wa.x,paB0); FMA2(paB1,u0B,wa.y,paB1); FMA2(paB2,u0B,wb.x,paB2); FMA2(paB3,u0B,wb.y,paB3); \
    FMA2(paB4,u0B,wc.x,paB4); FMA2(paB5,u0B,wc.y,paB5); FMA2(paB6,u0B,wd.x,paB6); FMA2(paB7,u0B,wd.y,paB7); \
    FMA2(pbB0,u1B,wa.x,pbB0); FMA2(pbB1,u1B,wa.y,pbB1); FMA2(pbB2,u1B,wb.x,pbB2); FMA2(pbB3,u1B,wb.y,pbB3); \
    FMA2(pbB4,u1B,wc.x,pbB4); FMA2(pbB5,u1B,wc.y,pbB5); FMA2(pbB6,u1B,wd.x,pbB6); FMA2(pbB7,u1B,wd.y,pbB7); \
    FMA2(pcB0,u2B,wa.x,pcB0); FMA2(pcB1,u2B,wa.y,pcB1); FMA2(pcB2,u2B,wb.x,pcB2); FMA2(pcB3,u2B,wb.y,pcB3); \
    FMA2(pcB4,u2B,wc.x,pcB4); FMA2(pcB5,u2B,wc.y,pcB5); FMA2(pcB6,u2B,wd.x,pcB6); FMA2(pcB7,u2B,wd.y,pcB7); }

// chunk c = k-values 4c..4c+3 : 8 exchange LDS.128 (both groups) + 2 KP steps
#define CHUNK(WB, c) { \
    const ulonglong2 hvA = ((const ulonglong2*)hSrcA)[c]; \
    const ulonglong2 u0A = ((const ulonglong2*)(tSrcA     ))[c]; \
    const ulonglong2 u1A = ((const ulonglong2*)(tSrcA + 32))[c]; \
    const ulonglong2 u2A = ((const ulonglong2*)(tSrcA + 64))[c]; \
    const ulonglong2 hvB = ((const ulonglong2*)hSrcB)[c]; \
    const ulonglong2 u0B = ((const ulonglong2*)(tSrcB     ))[c]; \
    const ulonglong2 u1B = ((const ulonglong2*)(tSrcB + 32))[c]; \
    const ulonglong2 u2B = ((const ulonglong2*)(tSrcB + 64))[c]; \
    KP(WB, 2*(c),     hvA.x, u0A.x, u1A.x, u2A.x, hvB.x, u0B.x, u1B.x, u2B.x) \
    KP(WB, 2*(c) + 1, hvA.y, u0A.y, u1A.y, u2A.y, hvB.y, u0B.y, u1B.y, u2B.y) }

#define LAYER(WB) \
    CHUNK(WB,0) CHUNK(WB,1) CHUNK(WB,2) CHUNK(WB,3) \
    CHUNK(WB,4) CHUNK(WB,5) CHUNK(WB,6) CHUNK(WB,7)

#define ZERO_T() \
    paA0=0ull;paA1=0ull;paA2=0ull;paA3=0ull;paA4=0ull;paA5=0ull;paA6=0ull;paA7=0ull; \
    pbA0=0ull;pbA1=0ull;pbA2=0ull;pbA3=0ull;pbA4=0ull;pbA5=0ull;pbA6=0ull;pbA7=0ull; \
    pcA0=0ull;pcA1=0ull;pcA2=0ull;pcA3=0ull;pcA4=0ull;pcA5=0ull;pcA6=0ull;pcA7=0ull; \
    paB0=0ull;paB1=0ull;paB2=0ull;paB3=0ull;paB4=0ull;paB5=0ull;paB6=0ull;paB7=0ull; \
    pbB0=0ull;pbB1=0ull;pbB2=0ull;pbB3=0ull;pbB4=0ull;pbB5=0ull;pbB6=0ull;pbB7=0ull; \
    pcB0=0ull;pcB1=0ull;pcB2=0ull;pcB3=0ull;pcB4=0ull;pcB5=0ull;pcB6=0ull;pcB7=0ull;

// exchange: 16 samples x 260 floats (1040B stride, = 16 mod 128)
#define SMP_F 260

__global__ __launch_bounds__(BLOCK, 7) void NCL_50766513438744_kernel(
    const float* __restrict__ x,
    const float* __restrict__ W1, const float* __restrict__ b1,
    const float* __restrict__ W2, const float* __restrict__ b2,
    const float* __restrict__ W3, const float* __restrict__ b3,
    const float* __restrict__ W4,
    float* __restrict__ out, int N)
{
    // blocked weights: (kp,q) block = 8 ulls (cols 8q..8q+7 as (W[2kp][c],W[2kp+1][c])),
    // padded to 10 ulls (80B, 16B-aligned): q offsets {0,80,32,112} mod 128
    __shared__ __align__(16) ull sW2u[640], sW3u[640];
    __shared__ __align__(16) float sCW1[96], sCB[96], sCW4[96];
    __shared__ __align__(16) float sBuf[16 * SMP_F];

    {
        const int t = threadIdx.x;
        for (int idx = t; idx < 1024; idx += BLOCK) {
            const int k = idx >> 5, m = idx & 31;
            const int uidx = ((k >> 1) * 4 + (m >> 3)) * 10 + (m & 7);
            const int fidx = uidx * 2 + (k & 1);
            ((float*)sW2u)[fidx] = W2[idx];
            ((float*)sW3u)[fidx] = W3[idx];
        }
        if (t < 32) {
            sCW1[t] = W1[t]; sCW1[32 + t] = W1[32 + t]; sCW1[64 + t] = W1[64 + t];
            sCB[t] = b1[t];  sCB[32 + t] = b2[t];       sCB[64 + t] = b3[t];
            sCW4[t] = W4[t * 3 + 0]; sCW4[32 + t] = W4[t * 3 + 1]; sCW4[64 + t] = W4[t * 3 + 2];
        }
    }
    __syncwarp();

    const int lane = threadIdx.x & 31;
    const int smp  = lane >> 2;          // sample slot 0..7 (group A); +8 = group B
    const int q    = lane & 3;           // column octet: cols 8q..8q+7

    float* const bufA = &sBuf[smp * SMP_F];
    float* const bufB = &sBuf[(smp + 8) * SMP_F];
    // per-buffer offsets: hb1=+0, hb2=+32, tb1=+64, tb2=+160

    const float4* const F4W1 = (const float4*)sCW1;
    const float4* const F4B  = (const float4*)sCB;
    const float4* const F4W4 = (const float4*)sCW4;

    const int nGroups = (N + 15) >> 4;
    const int gw = blockIdx.x;
    if (gw >= nGroups) return;

    int iA = 16 * gw + smp;     if (iA >= N) iA = N - 1;
    int iB = 16 * gw + 8 + smp; if (iB >= N) iB = N - 1;
    float xA0 = __ldg(x + 3 * iA + 0), xA1 = __ldg(x + 3 * iA + 1), xA2 = __ldg(x + 3 * iA + 2);
    float xB0 = __ldg(x + 3 * iB + 0), xB1 = __ldg(x + 3 * iB + 1), xB2 = __ldg(x + 3 * iB + 2);

    for (int g = gw; g < nGroups; g += GRID) {
        const int sA = 16 * g + smp;
        const int sB = 16 * g + 8 + smp;

        // ===== phase A: layer 1 + tangent seeds (both samples, 8 cols each) =====
        {
            const float4 r0a = F4W1[2*q],      r0b = F4W1[2*q + 1];
            const float4 r1a = F4W1[8 + 2*q],  r1b = F4W1[9 + 2*q];
            const float4 r2a = F4W1[16 + 2*q], r2b = F4W1[17 + 2*q];
            const float4 ba  = F4B[2*q],       bb  = F4B[2*q + 1];
#define PHASE_A(XP0, XP1, XP2, BUF) { \
            float4 h4a, h4b, d4a, d4b; \
            float z_; \
            z_ = fmaf(XP0, r0a.x, fmaf(XP1, r1a.x, fmaf(XP2, r2a.x, ba.x))); act_hd(z_, h4a.x, d4a.x); \
            z_ = fmaf(XP0, r0a.y, fmaf(XP1, r1a.y, fmaf(XP2, r2a.y, ba.y))); act_hd(z_, h4a.y, d4a.y); \
            z_ = fmaf(XP0, r0a.z, fmaf(XP1, r1a.z, fmaf(XP2, r2a.z, ba.z))); act_hd(z_, h4a.z, d4a.z); \
            z_ = fmaf(XP0, r0a.w, fmaf(XP1, r1a.w, fmaf(XP2, r2a.w, ba.w))); act_hd(z_, h4a.w, d4a.w); \
            z_ = fmaf(XP0, r0b.x, fmaf(XP1, r1b.x, fmaf(XP2, r2b.x, bb.x))); act_hd(z_, h4b.x, d4b.x); \
            z_ = fmaf(XP0, r0b.y, fmaf(XP1, r1b.y, fmaf(XP2, r2b.y, bb.y))); act_hd(z_, h4b.y, d4b.y); \
            z_ = fmaf(XP0, r0b.z, fmaf(XP1, r1b.z, fmaf(XP2, r2b.z, bb.z))); act_hd(z_, h4b.z, d4b.z); \
            z_ = fmaf(XP0, r0b.w, fmaf(XP1, r1b.w, fmaf(XP2, r2b.w, bb.w))); act_hd(z_, h4b.w, d4b.w); \
            ((float4*)(BUF))[2*q]          = h4a; \
            ((float4*)(BUF))[2*q + 1]      = h4b; \
            ((float4*)(BUF + 64))[2*q]     = make_float4(d4a.x*r0a.x, d4a.y*r0a.y, d4a.z*r0a.z, d4a.w*r0a.w); \
            ((float4*)(BUF + 64))[2*q + 1] = make_float4(d4b.x*r0b.x, d4b.y*r0b.y, d4b.z*r0b.z, d4b.w*r0b.w); \
            ((float4*)(BUF + 64))[8 + 2*q] = make_float4(d4a.x*r1a.x, d4a.y*r1a.y, d4a.z*r1a.z, d4a.w*r1a.w); \
            ((float4*)(BUF + 64))[9 + 2*q] = make_float4(d4b.x*r1b.x, d4b.y*r1b.y, d4b.z*r1b.z, d4b.w*r1b.w); \
            ((float4*)(BUF + 64))[16 + 2*q] = make_float4(d4a.x*r2a.x, d4a.y*r2a.y, d4a.z*r2a.z, d4a.w*r2a.w); \
            ((float4*)(BUF + 64))[17 + 2*q] = make_float4(d4b.x*r2b.x, d4b.y*r2b.y, d4b.z*r2b.z, d4b.w*r2b.w); }
            PHASE_A(xA0, xA1, xA2, bufA)
            PHASE_A(xB0, xB1, xB2, bufB)
#undef PHASE_A
        }
        __syncwarp();

        // prefetch next group's x (both samples)
        {
            const int gn = g + GRID;
            int nA = 16 * gn + smp;     if (nA >= N) nA = N - 1;
            int nB = 16 * gn + 8 + smp; if (nB >= N) nB = N - 1;
            xA0 = __ldg(x + 3 * nA + 0); xA1 = __ldg(x + 3 * nA + 1); xA2 = __ldg(x + 3 * nA + 2);
            xB0 = __ldg(x + 3 * nB + 0); xB1 = __ldg(x + 3 * nB + 1); xB2 = __ldg(x + 3 * nB + 2);
        }

        // ===== phase B: layer-2 forward + tangent layer 2 (both groups) =====
        ull fA0, fA1, fA2, fA3, fA4, fA5, fA6, fA7;
        ull fB0, fB1, fB2, fB3, fB4, fB5, fB6, fB7;
        {
            const float4 ba = F4B[8 + 2*q], bb = F4B[9 + 2*q];   // b2
            fA0 = pk2(ba.x, 0.f); fA1 = pk2(ba.y, 0.f); fA2 = pk2(ba.z, 0.f); fA3 = pk2(ba.w, 0.f);
            fA4 = pk2(bb.x, 0.f); fA5 = pk2(bb.y, 0.f); fA6 = pk2(bb.z, 0.f); fA7 = pk2(bb.w, 0.f);
            fB0 = pk2(ba.x, 0.f); fB1 = pk2(ba.y, 0.f); fB2 = pk2(ba.z, 0.f); fB3 = pk2(ba.w, 0.f);
            fB4 = pk2(bb.x, 0.f); fB5 = pk2(bb.y, 0.f); fB6 = pk2(bb.z, 0.f); fB7 = pk2(bb.w, 0.f);
        }
        ull paA0,paA1,paA2,paA3,paA4,paA5,paA6,paA7,
            pbA0,pbA1,pbA2,pbA3,pbA4,pbA5,pbA6,pbA7,
            pcA0,pcA1,pcA2,pcA3,pcA4,pcA5,pcA6,pcA7,
            paB0,paB1,paB2,paB3,paB4,paB5,paB6,paB7,
            pbB0,pbB1,pbB2,pbB3,pbB4,pbB5,pbB6,pbB7,
            pcB0,pcB1,pcB2,pcB3,pcB4,pcB5,pcB6,pcB7;
        ZERO_T()
        {
            const float* hSrcA = bufA;        const float* tSrcA = bufA + 64;
            const float* hSrcB = bufB;        const float* tSrcB = bufB + 64;
            LAYER(sW2u)
        }
        {
#define EPI_B(FP0,FP1,FP2,FP3,FP4,FP5,FP6,FP7, PA0,PA1,PA2,PA3,PA4,PA5,PA6,PA7, \
              PB0,PB1,PB2,PB3,PB4,PB5,PB6,PB7, PC0,PC1,PC2,PC3,PC4,PC5,PC6,PC7, BUF) { \
            float4 h4a, h4b, d4a, d4b; \
            act_hd(hadd2(FP0), h4a.x, d4a.x); act_hd(hadd2(FP1), h4a.y, d4a.y); \
            act_hd(hadd2(FP2), h4a.z, d4a.z); act_hd(hadd2(FP3), h4a.w, d4a.w); \
            act_hd(hadd2(FP4), h4b.x, d4b.x); act_hd(hadd2(FP5), h4b.y, d4b.y); \
            act_hd(hadd2(FP6), h4b.z, d4b.z); act_hd(hadd2(FP7), h4b.w, d4b.w); \
            ((float4*)(BUF + 32))[2*q]     = h4a; \
            ((float4*)(BUF + 32))[2*q + 1] = h4b; \
            ((float4*)(BUF + 160))[2*q]      = make_float4(d4a.x*hadd2(PA0), d4a.y*hadd2(PA1), d4a.z*hadd2(PA2), d4a.w*hadd2(PA3)); \
            ((float4*)(BUF + 160))[2*q + 1]  = make_float4(d4b.x*hadd2(PA4), d4b.y*hadd2(PA5), d4b.z*hadd2(PA6), d4b.w*hadd2(PA7)); \
            ((float4*)(BUF + 160))[8 + 2*q]  = make_float4(d4a.x*hadd2(PB0), d4a.y*hadd2(PB1), d4a.z*hadd2(PB2), d4a.w*hadd2(PB3)); \
            ((float4*)(BUF + 160))[9 + 2*q]  = make_float4(d4b.x*hadd2(PB4), d4b.y*hadd2(PB5), d4b.z*hadd2(PB6), d4b.w*hadd2(PB7)); \
            ((float4*)(BUF + 160))[16 + 2*q] = make_float4(d4a.x*hadd2(PC0), d4a.y*hadd2(PC1), d4a.z*hadd2(PC2), d4a.w*hadd2(PC3)); \
            ((float4*)(BUF + 160))[17 + 2*q] = make_float4(d4b.x*hadd2(PC4), d4b.y*hadd2(PC5), d4b.z*hadd2(PC6), d4b.w*hadd2(PC7)); }
            EPI_B(fA0,fA1,fA2,fA3,fA4,fA5,fA6,fA7,
                  paA0,paA1,paA2,paA3,paA4,paA5,paA6,paA7,
                  pbA0,pbA1,pbA2,pbA3,pbA4,pbA5,pbA6,pbA7,
                  pcA0,pcA1,pcA2,pcA3,pcA4,pcA5,pcA6,pcA7, bufA)
            EPI_B(fB0,fB1,fB2,fB3,fB4,fB5,fB6,fB7,
                  paB0,paB1,paB2,paB3,paB4,paB5,paB6,paB7,
                  pbB0,pbB1,pbB2,pbB3,pbB4,pbB5,pbB6,pbB7,
                  pcB0,pcB1,pcB2,pcB3,pcB4,pcB5,pcB6,pcB7, bufB)
#undef EPI_B
        }
        __syncwarp();

        // ===== phase C: layer-3 forward (deriv only) + tangent layer 3 =====
        {
            const float4 ba = F4B[16 + 2*q], bb = F4B[17 + 2*q];  // b3
            fA0 = pk2(ba.x, 0.f); fA1 = pk2(ba.y, 0.f); fA2 = pk2(ba.z, 0.f); fA3 = pk2(ba.w, 0.f);
            fA4 = pk2(bb.x, 0.f); fA5 = pk2(bb.y, 0.f); fA6 = pk2(bb.z, 0.f); fA7 = pk2(bb.w, 0.f);
            fB0 = pk2(ba.x, 0.f); fB1 = pk2(ba.y, 0.f); fB2 = pk2(ba.z, 0.f); fB3 = pk2(ba.w, 0.f);
            fB4 = pk2(bb.x, 0.f); fB5 = pk2(bb.y, 0.f); fB6 = pk2(bb.z, 0.f); fB7 = pk2(bb.w, 0.f);
        }
        ZERO_T()
        {
            const float* hSrcA = bufA + 32;   const float* tSrcA = bufA + 160;
            const float* hSrcB = bufB + 32;   const float* tSrcB = bufB + 160;
            LAYER(sW3u)
        }
        {
            const float4 wa0 = F4W4[2*q],      wb0 = F4W4[2*q + 1];
            const float4 wa1 = F4W4[8 + 2*q],  wb1 = F4W4[9 + 2*q];
            const float4 wa2 = F4W4[16 + 2*q], wb2 = F4W4[17 + 2*q];
            float po0A, po1A, po2A, po0B, po1B, po2B;
#define EPI_C(FP0,FP1,FP2,FP3,FP4,FP5,FP6,FP7, PA0,PA1,PA2,PA3,PA4,PA5,PA6,PA7, \
              PB0,PB1,PB2,PB3,PB4,PB5,PB6,PB7, PC0,PC1,PC2,PC3,PC4,PC5,PC6,PC7, \
              PO0, PO1, PO2) { \
            const float d0 = act_d(hadd2(FP0)), d1 = act_d(hadd2(FP1)); \
            const float d2 = act_d(hadd2(FP2)), d3 = act_d(hadd2(FP3)); \
            const float d4 = act_d(hadd2(FP4)), d5 = act_d(hadd2(FP5)); \
            const float d6 = act_d(hadd2(FP6)), d7 = act_d(hadd2(FP7)); \
            const float s00 = d0*hadd2(PA0), s01 = d1*hadd2(PA1), s02 = d2*hadd2(PA2), s03 = d3*hadd2(PA3); \
            const float s04 = d4*hadd2(PA4), s05 = d5*hadd2(PA5), s06 = d6*hadd2(PA6), s07 = d7*hadd2(PA7); \
            const float s10 = d0*hadd2(PB0), s11 = d1*hadd2(PB1), s12 = d2*hadd2(PB2), s13 = d3*hadd2(PB3); \
            const float s14 = d4*hadd2(PB4), s15 = d5*hadd2(PB5), s16 = d6*hadd2(PB6), s17 = d7*hadd2(PB7); \
            const float s20 = d0*hadd2(PC0), s21 = d1*hadd2(PC1), s22 = d2*hadd2(PC2), s23 = d3*hadd2(PC3); \
            const float s24 = d4*hadd2(PC4), s25 = d5*hadd2(PC5), s26 = d6*hadd2(PC6), s27 = d7*hadd2(PC7); \
            PO0 = fmaf(s10, wa0.x, s20 * wa1.x) + fmaf(s11, wa0.y, s21 * wa1.y) \
                + fmaf(s12, wa0.z, s22 * wa1.z) + fmaf(s13, wa0.w, s23 * wa1.w) \
                + fmaf(s14, wb0.x, s24 * wb1.x) + fmaf(s15, wb0.y, s25 * wb1.y) \
                + fmaf(s16, wb0.z, s26 * wb1.z) + fmaf(s17, wb0.w, s27 * wb1.w); \
            PO1 = fmaf(s20, wa2.x, -(s00 * wa0.x)) + fmaf(s21, wa2.y, -(s01 * wa0.y)) \
                + fmaf(s22, wa2.z, -(s02 * wa0.z)) + fmaf(s23, wa2.w, -(s03 * wa0.w)) \
                + fmaf(s24, wb2.x, -(s04 * wb0.x)) + fmaf(s25, wb2.y, -(s05 * wb0.y)) \
                + fmaf(s26, wb2.z, -(s06 * wb0.z)) + fmaf(s27, wb2.w, -(s07 * wb0.w)); \
            PO2 = -(fmaf(s00, wa1.x, s10 * wa2.x) + fmaf(s01, wa1.y, s11 * wa2.y) \
                  + fmaf(s02, wa1.z, s12 * wa2.z) + fmaf(s03, wa1.w, s13 * wa2.w) \
                  + fmaf(s04, wb1.x, s14 * wb2.x) + fmaf(s05, wb1.y, s15 * wb2.y) \
                  + fmaf(s06, wb1.z, s16 * wb2.z) + fmaf(s07, wb1.w, s17 * wb2.w)); }
            EPI_C(fA0,fA1,fA2,fA3,fA4,fA5,fA6,fA7,
                  paA0,paA1,paA2,paA3,paA4,paA5,paA6,paA7,
                  pbA0,pbA1,pbA2,pbA3,pbA4,pbA5,pbA6,pbA7,
                  pcA0,pcA1,pcA2,pcA3,pcA4,pcA5,pcA6,pcA7, po0A, po1A, po2A)
            EPI_C(fB0,fB1,fB2,fB3,fB4,fB5,fB6,fB7,
                  paB0,paB1,paB2,paB3,paB4,paB5,paB6,paB7,
                  pbB0,pbB1,pbB2,pbB3,pbB4,pbB5,pbB6,pbB7,
                  pcB0,pcB1,pcB2,pcB3,pcB4,pcB5,pcB6,pcB7, po0B, po1B, po2B)
#undef EPI_C

            // reduce over the 4 lanes of each sample's quartet
            #pragma unroll
            for (int off = 1; off <= 2; off <<= 1) {
                po0A += __shfl_xor_sync(0xffffffffu, po0A, off);
                po1A += __shfl_xor_sync(0xffffffffu, po1A, off);
                po2A += __shfl_xor_sync(0xffffffffu, po2A, off);
                po0B += __shfl_xor_sync(0xffffffffu, po0B, off);
                po1B += __shfl_xor_sync(0xffffffffu, po1B, off);
                po2B += __shfl_xor_sync(0xffffffffu, po2B, off);
            }
            if (q == 0) {
                if (sA < N) {
                    out[3 * sA + 0] = po0A;
                    out[3 * sA + 1] = po1A;
                    out[3 * sA + 2] = po2A;
                }
                if (sB < N) {
                    out[3 * sB + 0] = po0B;
                    out[3 * sB + 1] = po1B;
                    out[3 * sB + 2] = po2B;
                }
            }
        }
        // loop-carried buffer hazards covered by the syncwarps above
    }
}

extern "C" void kernel_launch(void* const* d_in, const int* in_sizes, int n_in,
                              void* d_out, int out_size) {
    const float* x  = (const float*)d_in[0];
    const float* W1 = (const float*)d_in[1];
    const float* b1 = (const float*)d_in[2];
    const float* W2 = (const float*)d_in[3];
    const float* b2 = (const float*)d_in[4];
    const float* W3 = (const float*)d_in[5];
    const float* b3 = (const float*)d_in[6];
    const float* W4 = (const float*)d_in[7];
    // d_in[8] = b4: not needed (bias drops out of the Jacobian)
    float* out = (float*)d_out;

    const int N = in_sizes[0] / 3;
    NCL_50766513438744_kernel<<<GRID, BLOCK>>>(x, W1, b1, W2, b2, W3, b3, W4, out, N);
}